// round 6
// baseline (speedup 1.0000x reference)
#include <cuda_runtime.h>
#include <stdint.h>

#define BB 2
#define NN 2048
#define EE 1024
#define HH 16
#define DD 64
#define MTOT (BB * NN)

// swizzle for B-operand tiles (row width 64/128 floats): xors bits 2-4 of n with k
#define BXOR(k) (((((k) & 3) << 3)) | ((((k) & 4) << 2)))

// ---------------------------------------------------------------------------
// Scratch
// ---------------------------------------------------------------------------
__device__ float g_q [BB * HH * NN * DD];
__device__ float g_k [BB * HH * NN * DD];
__device__ float g_v [BB * HH * NN * DD];
__device__ float g_ao[(size_t)MTOT * EE];

// ---------------------------------------------------------------------------
// Helpers
// ---------------------------------------------------------------------------
__device__ __forceinline__ uint32_t f2tf(float x) {
    uint32_t u;
    asm("cvt.rna.tf32.f32 %0, %1;" : "=r"(u) : "f"(x));
    return u;
}

// 3xTF32 split: x ~= hi + lo, both representable in tf32
__device__ __forceinline__ void tfsplit(float x, uint32_t& hi, uint32_t& lo) {
    hi = f2tf(x);
    lo = f2tf(x - __uint_as_float(hi));
}

__device__ __forceinline__ void mma8(float& c0, float& c1, float& c2, float& c3,
                                     uint32_t a0, uint32_t a1, uint32_t a2, uint32_t a3,
                                     uint32_t b0, uint32_t b1) {
    asm volatile(
        "mma.sync.aligned.m16n8k8.row.col.f32.tf32.tf32.f32 "
        "{%0,%1,%2,%3}, {%4,%5,%6,%7}, {%8,%9}, {%0,%1,%2,%3};\n"
        : "+f"(c0), "+f"(c1), "+f"(c2), "+f"(c3)
        : "r"(a0), "r"(a1), "r"(a2), "r"(a3), "r"(b0), "r"(b1));
}

// C += A*B with 3xtf32 compensation: Alo*Bhi + Ahi*Blo + Ahi*Bhi
__device__ __forceinline__ void mma8_3x(float* c,
                                        const uint32_t* ah, const uint32_t* al,
                                        const uint32_t* bh, const uint32_t* bl) {
    mma8(c[0], c[1], c[2], c[3], al[0], al[1], al[2], al[3], bh[0], bh[1]);
    mma8(c[0], c[1], c[2], c[3], ah[0], ah[1], ah[2], ah[3], bl[0], bl[1]);
    mma8(c[0], c[1], c[2], c[3], ah[0], ah[1], ah[2], ah[3], bh[0], bh[1]);
}

// ---------------------------------------------------------------------------
// 3xtf32 GEMM: Y[m,e] = X[m,:] . W[e,:] + bias[e]
// BM=128 BN=128 BK=32, 8 warps (2x4), warp tile 64x32, mma m16n8k8.
// hi/lo PRE-SPLIT into smem at tile load; inner loop is pure LDS + MMA.
// ---------------------------------------------------------------------------
template<int SCATTER>
__global__ __launch_bounds__(256, 2)
void gemm_tf32(const float* __restrict__ X,
               const float* __restrict__ W,
               const float* __restrict__ bias,
               float* __restrict__ Y)
{
    extern __shared__ uint32_t gsm[];
    uint32_t* Ah = gsm;                 // [m][k^((m&7)<<2)]  128*32
    uint32_t* Al = Ah + 128 * 32;
    uint32_t* Bh = Al + 128 * 32;       // [k][n^BXOR(k)]     32*128
    uint32_t* Bl = Bh + 32 * 128;

    const int tid  = threadIdx.x;
    const int lane = tid & 31;
    const int warp = tid >> 5;
    const int wm = warp >> 2, wn = warp & 3;
    const int g = lane >> 2, t4 = lane & 3;
    const int m0 = blockIdx.y * 128, n0 = blockIdx.x * 128;

    const int aRow = tid >> 3, aK4 = tid & 7;   // A loader
    const int bN = tid >> 1, bKh = tid & 1;     // B loader

    float acc[4][4][4];
    #pragma unroll
    for (int i = 0; i < 4; ++i)
        #pragma unroll
        for (int j = 0; j < 4; ++j)
            #pragma unroll
            for (int c = 0; c < 4; ++c) acc[i][j][c] = 0.f;

    const float* Xb = X + (size_t)m0 * EE;
    const float* Wb = W + (size_t)n0 * EE;

    for (int kt = 0; kt < EE; kt += 32) {
        __syncthreads();
        #pragma unroll
        for (int i = 0; i < 4; ++i) {
            const int m = aRow + 32 * i;
            float4 v = *(const float4*)(Xb + (size_t)m * EE + kt + aK4 * 4);
            uint4 uh, ul;
            tfsplit(v.x, uh.x, ul.x);
            tfsplit(v.y, uh.y, ul.y);
            tfsplit(v.z, uh.z, ul.z);
            tfsplit(v.w, uh.w, ul.w);
            const int idx = m * 32 + ((aK4 * 4) ^ ((m & 7) << 2));
            *(uint4*)(&Ah[idx]) = uh;
            *(uint4*)(&Al[idx]) = ul;
        }
        #pragma unroll
        for (int j = 0; j < 4; ++j) {
            const int kb = (2 * j + bKh) * 4;
            float4 v = *(const float4*)(Wb + (size_t)bN * EE + kt + kb);
            uint32_t h0, l0;
            tfsplit(v.x, h0, l0);
            Bh[(kb + 0) * 128 + (bN ^ BXOR(kb + 0))] = h0;
            Bl[(kb + 0) * 128 + (bN ^ BXOR(kb + 0))] = l0;
            tfsplit(v.y, h0, l0);
            Bh[(kb + 1) * 128 + (bN ^ BXOR(kb + 1))] = h0;
            Bl[(kb + 1) * 128 + (bN ^ BXOR(kb + 1))] = l0;
            tfsplit(v.z, h0, l0);
            Bh[(kb + 2) * 128 + (bN ^ BXOR(kb + 2))] = h0;
            Bl[(kb + 2) * 128 + (bN ^ BXOR(kb + 2))] = l0;
            tfsplit(v.w, h0, l0);
            Bh[(kb + 3) * 128 + (bN ^ BXOR(kb + 3))] = h0;
            Bl[(kb + 3) * 128 + (bN ^ BXOR(kb + 3))] = l0;
        }
        __syncthreads();

        #pragma unroll
        for (int kk = 0; kk < 4; ++kk) {
            const int c0 = kk * 8 + t4;
            uint32_t bhf[4][2], blf[4][2];
            #pragma unroll
            for (int nt = 0; nt < 4; ++nt) {
                const int nb = wn * 32 + nt * 8 + g;
                const int i0 = c0 * 128 + (nb ^ BXOR(c0));
                const int i1 = (c0 + 4) * 128 + (nb ^ BXOR(c0 + 4));
                bhf[nt][0] = Bh[i0]; blf[nt][0] = Bl[i0];
                bhf[nt][1] = Bh[i1]; blf[nt][1] = Bl[i1];
            }
            #pragma unroll
            for (int mt = 0; mt < 4; ++mt) {
                const int r0 = wm * 64 + mt * 16 + g;
                const int x = (r0 & 7) << 2;
                const int i0 = r0 * 32 + (c0 ^ x);
                const int i1 = (r0 + 8) * 32 + (c0 ^ x);
                const int i2 = r0 * 32 + ((c0 + 4) ^ x);
                const int i3 = (r0 + 8) * 32 + ((c0 + 4) ^ x);
                uint32_t ah[4] = {Ah[i0], Ah[i1], Ah[i2], Ah[i3]};
                uint32_t al[4] = {Al[i0], Al[i1], Al[i2], Al[i3]};
                #pragma unroll
                for (int nt = 0; nt < 4; ++nt)
                    mma8_3x(acc[mt][nt], ah, al, bhf[nt], blf[nt]);
            }
        }
    }

    #pragma unroll
    for (int mt = 0; mt < 4; ++mt) {
        const int r0 = m0 + wm * 64 + mt * 16 + g;
        #pragma unroll
        for (int nt = 0; nt < 4; ++nt) {
            const int c = n0 + wn * 32 + nt * 8 + 2 * t4;
            const float bv0 = bias[c], bv1 = bias[c + 1];
            float2 v0 = make_float2(acc[mt][nt][0] + bv0, acc[mt][nt][1] + bv1);
            float2 v1 = make_float2(acc[mt][nt][2] + bv0, acc[mt][nt][3] + bv1);
            if (SCATTER) {
                const int h = c >> 6, d = c & 63;
                const int b0i = r0 >> 11, n0i = r0 & (NN - 1);
                *(float2*)(&Y[((((size_t)b0i * HH + h) * NN) + n0i) * DD + d]) = v0;
                const int r1 = r0 + 8;
                const int b1i = r1 >> 11, n1i = r1 & (NN - 1);
                *(float2*)(&Y[((((size_t)b1i * HH + h) * NN) + n1i) * DD + d]) = v1;
            } else {
                *(float2*)(&Y[(size_t)r0 * EE + c]) = v0;
                *(float2*)(&Y[(size_t)(r0 + 8) * EE + c]) = v1;
            }
        }
    }
}

// ---------------------------------------------------------------------------
// Flash attention. BQ=64, BKV=64, 8 warps (2x4).
// mma1 (3xtf32): S^T[kv][q] = K . Q^T    K,Q pre-split hi/lo in smem
// softmax column-wise over kv (online m/l), quirk: /sqrt(E)=32 post-softmax
// mma2 (1xtf32): O[q][d] += P . V        P,V stored tf32-rounded (error ~1e-4)
// ---------------------------------------------------------------------------
__global__ __launch_bounds__(256)
void flash_tf32(const float* __restrict__ qb,
                const float* __restrict__ kb,
                const float* __restrict__ vb,
                float* __restrict__ out)
{
    extern __shared__ char smraw[];
    uint32_t* Qh = (uint32_t*)smraw;       // [d][q ^ BXOR(d)]
    uint32_t* Ql = Qh + 64 * 64;
    uint32_t* Kh = Ql + 64 * 64;           // [kv][d ^ ((kv&7)<<2)]
    uint32_t* Kl = Kh + 64 * 64;
    uint32_t* Vs = Kl + 64 * 64;           // [kv][d ^ BXOR(kv)]  tf32-rounded
    float*    St = (float*)(Vs + 64 * 64); // [kv][q ^ ((kv&3)<<3)]
    float* mrow = St + 64 * 64;
    float* lrow = mrow + 64;
    float* arow = lrow + 64;
    float* pmax = arow + 64;               // [4][64]
    float* psum = pmax + 256;              // [4][64]

    const int tid  = threadIdx.x;
    const int lane = tid & 31;
    const int warp = tid >> 5;
    const int wm = warp >> 2, wn = warp & 3;
    const int g = lane >> 2, t4 = lane & 3;

    const int q0 = blockIdx.x * 64;
    const int bh = blockIdx.y;
    const int b  = bh >> 4;
    const int h  = bh & (HH - 1);

    if (tid < 64) { mrow[tid] = -1e30f; lrow[tid] = 0.f; }

    // Q transpose + hi/lo split (once per block, reused 32 tiles)
    const float* Qg = qb + ((size_t)bh * NN + q0) * DD;
    const int d4 = tid & 15, row0 = tid >> 4;
    #pragma unroll
    for (int i = 0; i < 4; ++i) {
        const int q = row0 + 16 * i;
        float4 v = *(const float4*)(Qg + (size_t)q * DD + d4 * 4);
        const int dd = d4 * 4;
        uint32_t hh, ll;
        tfsplit(v.x, hh, ll);
        Qh[(dd + 0) * 64 + (q ^ BXOR(dd + 0))] = hh;
        Ql[(dd + 0) * 64 + (q ^ BXOR(dd + 0))] = ll;
        tfsplit(v.y, hh, ll);
        Qh[(dd + 1) * 64 + (q ^ BXOR(dd + 1))] = hh;
        Ql[(dd + 1) * 64 + (q ^ BXOR(dd + 1))] = ll;
        tfsplit(v.z, hh, ll);
        Qh[(dd + 2) * 64 + (q ^ BXOR(dd + 2))] = hh;
        Ql[(dd + 2) * 64 + (q ^ BXOR(dd + 2))] = ll;
        tfsplit(v.w, hh, ll);
        Qh[(dd + 3) * 64 + (q ^ BXOR(dd + 3))] = hh;
        Ql[(dd + 3) * 64 + (q ^ BXOR(dd + 3))] = ll;
    }

    float oacc[2][2][4];
    #pragma unroll
    for (int i = 0; i < 2; ++i)
        #pragma unroll
        for (int j = 0; j < 2; ++j)
            #pragma unroll
            for (int c = 0; c < 4; ++c) oacc[i][j][c] = 0.f;

    const float* Kg = kb + (size_t)bh * NN * DD;
    const float* Vg = vb + (size_t)bh * NN * DD;

    for (int kv0 = 0; kv0 < NN; kv0 += 64) {
        __syncthreads();
        #pragma unroll
        for (int i = 0; i < 4; ++i) {
            const int kv = row0 + 16 * i;
            float4 kv4 = *(const float4*)(Kg + (size_t)(kv0 + kv) * DD + d4 * 4);
            float4 vv4 = *(const float4*)(Vg + (size_t)(kv0 + kv) * DD + d4 * 4);
            uint4 kh, kl;
            tfsplit(kv4.x, kh.x, kl.x);
            tfsplit(kv4.y, kh.y, kl.y);
            tfsplit(kv4.z, kh.z, kl.z);
            tfsplit(kv4.w, kh.w, kl.w);
            const int kidx = kv * 64 + ((d4 * 4) ^ ((kv & 7) << 2));
            *(uint4*)(&Kh[kidx]) = kh;
            *(uint4*)(&Kl[kidx]) = kl;
            uint4 vu = make_uint4(f2tf(vv4.x), f2tf(vv4.y), f2tf(vv4.z), f2tf(vv4.w));
            *(uint4*)(&Vs[kv * 64 + ((d4 * 4) ^ BXOR(kv))]) = vu;
        }
        __syncthreads();

        // mma1: S^T = K . Q^T  (3xtf32)
        float sacc[2][2][4];
        #pragma unroll
        for (int i = 0; i < 2; ++i)
            #pragma unroll
            for (int j = 0; j < 2; ++j)
                #pragma unroll
                for (int c = 0; c < 4; ++c) sacc[i][j][c] = 0.f;

        #pragma unroll
        for (int kk = 0; kk < 8; ++kk) {
            const int c0 = kk * 8 + t4;
            uint32_t ah[2][4], al[2][4];
            #pragma unroll
            for (int mt = 0; mt < 2; ++mt) {
                const int r0 = wm * 32 + mt * 16 + g;
                const int x = (r0 & 7) << 2;
                const int i0 = r0 * 64 + (c0 ^ x);
                const int i1 = (r0 + 8) * 64 + (c0 ^ x);
                const int i2 = r0 * 64 + ((c0 + 4) ^ x);
                const int i3 = (r0 + 8) * 64 + ((c0 + 4) ^ x);
                ah[mt][0] = Kh[i0]; al[mt][0] = Kl[i0];
                ah[mt][1] = Kh[i1]; al[mt][1] = Kl[i1];
                ah[mt][2] = Kh[i2]; al[mt][2] = Kl[i2];
                ah[mt][3] = Kh[i3]; al[mt][3] = Kl[i3];
            }
            uint32_t bh_[2][2], bl_[2][2];
            #pragma unroll
            for (int nt = 0; nt < 2; ++nt) {
                const int nb = wn * 16 + nt * 8 + g;
                const int i0 = c0 * 64 + (nb ^ BXOR(c0));
                const int i1 = (c0 + 4) * 64 + (nb ^ BXOR(c0 + 4));
                bh_[nt][0] = Qh[i0]; bl_[nt][0] = Ql[i0];
                bh_[nt][1] = Qh[i1]; bl_[nt][1] = Ql[i1];
            }
            #pragma unroll
            for (int mt = 0; mt < 2; ++mt)
                #pragma unroll
                for (int nt = 0; nt < 2; ++nt)
                    mma8_3x(sacc[mt][nt], ah[mt], al[mt], bh_[nt], bl_[nt]);
        }
        #pragma unroll
        for (int mt = 0; mt < 2; ++mt) {
            const int kvr = wm * 32 + mt * 16 + g;
            #pragma unroll
            for (int nt = 0; nt < 2; ++nt) {
                const int qc = wn * 16 + nt * 8 + 2 * t4;
                *(float2*)(&St[kvr * 64 + (qc ^ ((kvr & 3) << 3))]) =
                    make_float2(sacc[mt][nt][0], sacc[mt][nt][1]);
                *(float2*)(&St[(kvr + 8) * 64 + (qc ^ (((kvr + 8) & 3) << 3))]) =
                    make_float2(sacc[mt][nt][2], sacc[mt][nt][3]);
            }
        }
        __syncthreads();

        // online softmax over kv (columns of S^T); write back tf32-rounded p
        {
            const int q = tid & 63, kvg = tid >> 6;
            float sv[16];
            float mloc = -1e30f;
            #pragma unroll
            for (int r = 0; r < 16; ++r) {
                const int kv = kvg * 16 + r;
                sv[r] = St[kv * 64 + (q ^ ((kv & 3) << 3))];
                mloc = fmaxf(mloc, sv[r]);
            }
            pmax[kvg * 64 + q] = mloc;
            __syncthreads();
            const float mold = mrow[q];
            const float mnew = fmaxf(mold,
                fmaxf(fmaxf(pmax[q], pmax[64 + q]), fmaxf(pmax[128 + q], pmax[192 + q])));
            float sloc = 0.f;
            #pragma unroll
            for (int r = 0; r < 16; ++r) {
                const int kv = kvg * 16 + r;
                const float p = __expf(sv[r] - mnew);
                sloc += p;
                St[kv * 64 + (q ^ ((kv & 3) << 3))] = __uint_as_float(f2tf(p));
            }
            psum[kvg * 64 + q] = sloc;
            __syncthreads();
            if (kvg == 0) {
                const float alpha = __expf(mold - mnew);
                lrow[q] = lrow[q] * alpha + psum[q] + psum[64 + q] + psum[128 + q] + psum[192 + q];
                mrow[q] = mnew;
                arow[q] = alpha;
            }
            __syncthreads();
        }

        // rescale O accumulators
        #pragma unroll
        for (int mt = 0; mt < 2; ++mt) {
            const int qr = wm * 32 + mt * 16 + g;
            const float al0 = arow[qr], al1 = arow[qr + 8];
            #pragma unroll
            for (int nt = 0; nt < 2; ++nt) {
                oacc[mt][nt][0] *= al0; oacc[mt][nt][1] *= al0;
                oacc[mt][nt][2] *= al1; oacc[mt][nt][3] *= al1;
            }
        }

        // mma2: O += P . V  (single tf32 mma; P, V tf32-rounded)
        #pragma unroll
        for (int kk = 0; kk < 8; ++kk) {
            const int kvc = kk * 8 + t4;
            const int x0 = (kvc & 3) << 3;   // same for kvc and kvc+4
            uint32_t af[2][4];
            #pragma unroll
            for (int mt = 0; mt < 2; ++mt) {
                const int qr = wm * 32 + mt * 16 + g;
                af[mt][0] = __float_as_uint(St[kvc * 64 + (qr ^ x0)]);
                af[mt][1] = __float_as_uint(St[kvc * 64 + ((qr + 8) ^ x0)]);
                af[mt][2] = __float_as_uint(St[(kvc + 4) * 64 + (qr ^ x0)]);
                af[mt][3] = __float_as_uint(St[(kvc + 4) * 64 + ((qr + 8) ^ x0)]);
            }
            uint32_t bf[2][2];
            #pragma unroll
            for (int nt = 0; nt < 2; ++nt) {
                const int db = wn * 16 + nt * 8 + g;
                bf[nt][0] = Vs[kvc * 64 + (db ^ BXOR(kvc))];
                bf[nt][1] = Vs[(kvc + 4) * 64 + (db ^ BXOR(kvc + 4))];
            }
            #pragma unroll
            for (int mt = 0; mt < 2; ++mt)
                #pragma unroll
                for (int nt = 0; nt < 2; ++nt)
                    mma8(oacc[mt][nt][0], oacc[mt][nt][1], oacc[mt][nt][2], oacc[mt][nt][3],
                         af[mt][0], af[mt][1], af[mt][2], af[mt][3],
                         bf[nt][0], bf[nt][1]);
        }
    }

    // epilogue: /l, /sqrt(E)=32, merge heads
    #pragma unroll
    for (int mt = 0; mt < 2; ++mt) {
        const int qr = wm * 32 + mt * 16 + g;
        const float inv0 = 1.f / (lrow[qr] * 32.f);
        const float inv1 = 1.f / (lrow[qr + 8] * 32.f);
        #pragma unroll
        for (int nt = 0; nt < 2; ++nt) {
            const int dc = wn * 16 + nt * 8 + 2 * t4;
            *(float2*)(&out[((size_t)b * NN + q0 + qr) * EE + h * DD + dc]) =
                make_float2(oacc[mt][nt][0] * inv0, oacc[mt][nt][1] * inv0);
            *(float2*)(&out[((size_t)b * NN + q0 + qr + 8) * EE + h * DD + dc]) =
                make_float2(oacc[mt][nt][2] * inv1, oacc[mt][nt][3] * inv1);
        }
    }
}

// ---------------------------------------------------------------------------
// Launcher
// ---------------------------------------------------------------------------
extern "C" void kernel_launch(void* const* d_in, const int* in_sizes, int n_in,
                              void* d_out, int out_size)
{
    const float* queries = (const float*)d_in[0];
    const float* keys    = (const float*)d_in[1];
    const float* values  = (const float*)d_in[2];
    const float* Wq = (const float*)d_in[3];
    const float* bq = (const float*)d_in[4];
    const float* Wk = (const float*)d_in[5];
    const float* bk = (const float*)d_in[6];
    const float* Wv = (const float*)d_in[7];
    const float* bv = (const float*)d_in[8];
    const float* Wp = (const float*)d_in[9];
    const float* bp = (const float*)d_in[10];
    float* out = (float*)d_out;

    float *pq, *pk, *pv, *pao;
    cudaGetSymbolAddress((void**)&pq,  g_q);
    cudaGetSymbolAddress((void**)&pk,  g_k);
    cudaGetSymbolAddress((void**)&pv,  g_v);
    cudaGetSymbolAddress((void**)&pao, g_ao);

    const int gemm_smem = 4 * 128 * 32 * (int)sizeof(uint32_t); // 65536
    cudaFuncSetAttribute(gemm_tf32<1>,
                         cudaFuncAttributeMaxDynamicSharedMemorySize, gemm_smem);
    cudaFuncSetAttribute(gemm_tf32<0>,
                         cudaFuncAttributeMaxDynamicSharedMemorySize, gemm_smem);

    const dim3 gemm_grid(EE / 128, MTOT / 128);   // (8, 32)
    gemm_tf32<1><<<gemm_grid, 256, gemm_smem>>>(queries, Wq, bq, pq);
    gemm_tf32<1><<<gemm_grid, 256, gemm_smem>>>(keys,    Wk, bk, pk);
    gemm_tf32<1><<<gemm_grid, 256, gemm_smem>>>(values,  Wv, bv, pv);

    const int fa_smem = (6 * 64 * 64) * 4 + (3 * 64 + 2 * 256) * 4; // 101120
    cudaFuncSetAttribute(flash_tf32,
                         cudaFuncAttributeMaxDynamicSharedMemorySize, fa_smem);
    const dim3 fa_grid(NN / 64, BB * HH);         // (32, 32)
    flash_tf32<<<fa_grid, 256, fa_smem>>>(pq, pk, pv, pao);

    gemm_tf32<0><<<gemm_grid, 256, gemm_smem>>>(pao, Wp, bp, out);
}

// round 7
// speedup vs baseline: 1.4698x; 1.4698x over previous
#include <cuda_runtime.h>
#include <cuda_bf16.h>
#include <stdint.h>

#define BB 2
#define NN 2048
#define EE 1024
#define HH 16
#define DD 64
#define MTOT (BB * NN)

// swizzle for tf32 V tile (row width 64 floats)
#define BXOR(k) (((((k) & 3) << 3)) | ((((k) & 4) << 2)))

// ---------------------------------------------------------------------------
// Scratch
// ---------------------------------------------------------------------------
__device__ float g_q [BB * HH * NN * DD];
__device__ float g_k [BB * HH * NN * DD];
__device__ float g_v [BB * HH * NN * DD];
__device__ float g_ao[(size_t)MTOT * EE];

// ---------------------------------------------------------------------------
// Helpers
// ---------------------------------------------------------------------------
__device__ __forceinline__ uint32_t f2tf(float x) {
    uint32_t u;
    asm("cvt.rna.tf32.f32 %0, %1;" : "=r"(u) : "f"(x));
    return u;
}

// bf16 split: x ~= hi + lo (hi/lo both bf16-representable; lo captures next 8 bits)
__device__ __forceinline__ void bfsplit(float x, float& h, float& l) {
    h = __bfloat162float(__float2bfloat16(x));
    l = x - h;
}

// pack two floats to bf16x2 (low half = a, high half = b)
__device__ __forceinline__ uint32_t packbf(float a, float b) {
    __nv_bfloat162 t = __floats2bfloat162_rn(a, b);
    return *reinterpret_cast<uint32_t*>(&t);
}

// tf32 m16n8k8 (used only for PV)
__device__ __forceinline__ void mma8(float& c0, float& c1, float& c2, float& c3,
                                     uint32_t a0, uint32_t a1, uint32_t a2, uint32_t a3,
                                     uint32_t b0, uint32_t b1) {
    asm volatile(
        "mma.sync.aligned.m16n8k8.row.col.f32.tf32.tf32.f32 "
        "{%0,%1,%2,%3}, {%4,%5,%6,%7}, {%8,%9}, {%0,%1,%2,%3};\n"
        : "+f"(c0), "+f"(c1), "+f"(c2), "+f"(c3)
        : "r"(a0), "r"(a1), "r"(a2), "r"(a3), "r"(b0), "r"(b1));
}

// bf16 m16n8k16
__device__ __forceinline__ void mmabf(float& c0, float& c1, float& c2, float& c3,
                                      uint32_t a0, uint32_t a1, uint32_t a2, uint32_t a3,
                                      uint32_t b0, uint32_t b1) {
    asm volatile(
        "mma.sync.aligned.m16n8k16.row.col.f32.bf16.bf16.f32 "
        "{%0,%1,%2,%3}, {%4,%5,%6,%7}, {%8,%9}, {%0,%1,%2,%3};\n"
        : "+f"(c0), "+f"(c1), "+f"(c2), "+f"(c3)
        : "r"(a0), "r"(a1), "r"(a2), "r"(a3), "r"(b0), "r"(b1));
}

// C += A*B with 3xbf16 compensation: Alo*Bhi + Ahi*Blo + Ahi*Bhi
__device__ __forceinline__ void mmabf_3x(float* c,
                                         const uint32_t* ah, const uint32_t* al,
                                         const uint32_t* bh, const uint32_t* bl) {
    mmabf(c[0], c[1], c[2], c[3], al[0], al[1], al[2], al[3], bh[0], bh[1]);
    mmabf(c[0], c[1], c[2], c[3], ah[0], ah[1], ah[2], ah[3], bl[0], bl[1]);
    mmabf(c[0], c[1], c[2], c[3], ah[0], ah[1], ah[2], ah[3], bh[0], bh[1]);
}

// ---------------------------------------------------------------------------
// 3xbf16 GEMM: Y[m,e] = X[m,:] . W[e,:] + bias[e]
// BM=128 BN=128 BK=32, 8 warps (2x4), warp tile 64x32, mma m16n8k16.
// smem: bf16x2-packed hi/lo, [row][k2] (k2 = k/2, width 16), swizzle (row&7)<<1.
// ---------------------------------------------------------------------------
template<int SCATTER>
__global__ __launch_bounds__(256, 2)
void gemm_bf16(const float* __restrict__ X,
               const float* __restrict__ W,
               const float* __restrict__ bias,
               float* __restrict__ Y)
{
    extern __shared__ uint32_t gsm[];
    uint32_t* Ah = gsm;                 // [128][16]
    uint32_t* Al = Ah + 128 * 16;
    uint32_t* Bh = Al + 128 * 16;       // [128][16] (n rows)
    uint32_t* Bl = Bh + 128 * 16;

    const int tid  = threadIdx.x;
    const int lane = tid & 31;
    const int warp = tid >> 5;
    const int wm = warp >> 2, wn = warp & 3;
    const int g = lane >> 2, t4 = lane & 3;
    const int m0 = blockIdx.y * 128, n0 = blockIdx.x * 128;

    const int aRow = tid >> 3, aK4 = tid & 7;   // A loader
    const int bN = tid >> 1, bKh = tid & 1;     // B loader

    float acc[4][4][4];
    #pragma unroll
    for (int i = 0; i < 4; ++i)
        #pragma unroll
        for (int j = 0; j < 4; ++j)
            #pragma unroll
            for (int c = 0; c < 4; ++c) acc[i][j][c] = 0.f;

    const float* Xb = X + (size_t)m0 * EE;
    const float* Wb = W + (size_t)n0 * EE;

    for (int kt = 0; kt < EE; kt += 32) {
        __syncthreads();
        #pragma unroll
        for (int i = 0; i < 4; ++i) {
            const int m = aRow + 32 * i;
            float4 v = *(const float4*)(Xb + (size_t)m * EE + kt + aK4 * 4);
            float h0, l0, h1, l1, h2, l2, h3, l3;
            bfsplit(v.x, h0, l0); bfsplit(v.y, h1, l1);
            bfsplit(v.z, h2, l2); bfsplit(v.w, h3, l3);
            const int idx = m * 16 + ((aK4 * 2) ^ ((m & 7) << 1));
            *(uint2*)(&Ah[idx]) = make_uint2(packbf(h0, h1), packbf(h2, h3));
            *(uint2*)(&Al[idx]) = make_uint2(packbf(l0, l1), packbf(l2, l3));
        }
        #pragma unroll
        for (int j = 0; j < 4; ++j) {
            const int kb = (2 * j + bKh) * 4;
            float4 v = *(const float4*)(Wb + (size_t)bN * EE + kt + kb);
            float h0, l0, h1, l1, h2, l2, h3, l3;
            bfsplit(v.x, h0, l0); bfsplit(v.y, h1, l1);
            bfsplit(v.z, h2, l2); bfsplit(v.w, h3, l3);
            const int idx = bN * 16 + (((2 * j + bKh) * 2) ^ ((bN & 7) << 1));
            *(uint2*)(&Bh[idx]) = make_uint2(packbf(h0, h1), packbf(h2, h3));
            *(uint2*)(&Bl[idx]) = make_uint2(packbf(l0, l1), packbf(l2, l3));
        }
        __syncthreads();

        #pragma unroll
        for (int kk = 0; kk < 2; ++kk) {
            const int c = kk * 8 + t4;
            const int c2 = c + 4;
            uint32_t bhf[4][2], blf[4][2];
            #pragma unroll
            for (int nt = 0; nt < 4; ++nt) {
                const int nb = wn * 32 + nt * 8 + g;
                const int sw = (nb & 7) << 1;
                const int i0 = nb * 16 + (c ^ sw);
                const int i1 = nb * 16 + (c2 ^ sw);
                bhf[nt][0] = Bh[i0]; blf[nt][0] = Bl[i0];
                bhf[nt][1] = Bh[i1]; blf[nt][1] = Bl[i1];
            }
            #pragma unroll
            for (int mt = 0; mt < 4; ++mt) {
                const int r0 = wm * 64 + mt * 16 + g;
                const int sw = (r0 & 7) << 1;
                const int i0 = r0 * 16 + (c ^ sw);
                const int i1 = (r0 + 8) * 16 + (c ^ sw);
                const int i2 = r0 * 16 + (c2 ^ sw);
                const int i3 = (r0 + 8) * 16 + (c2 ^ sw);
                uint32_t ah[4] = {Ah[i0], Ah[i1], Ah[i2], Ah[i3]};
                uint32_t al[4] = {Al[i0], Al[i1], Al[i2], Al[i3]};
                #pragma unroll
                for (int nt = 0; nt < 4; ++nt)
                    mmabf_3x(acc[mt][nt], ah, al, bhf[nt], blf[nt]);
            }
        }
    }

    #pragma unroll
    for (int mt = 0; mt < 4; ++mt) {
        const int r0 = m0 + wm * 64 + mt * 16 + g;
        #pragma unroll
        for (int nt = 0; nt < 4; ++nt) {
            const int c = n0 + wn * 32 + nt * 8 + 2 * t4;
            const float bv0 = bias[c], bv1 = bias[c + 1];
            float2 v0 = make_float2(acc[mt][nt][0] + bv0, acc[mt][nt][1] + bv1);
            float2 v1 = make_float2(acc[mt][nt][2] + bv0, acc[mt][nt][3] + bv1);
            if (SCATTER) {
                const int h = c >> 6, d = c & 63;
                const int b0i = r0 >> 11, n0i = r0 & (NN - 1);
                *(float2*)(&Y[((((size_t)b0i * HH + h) * NN) + n0i) * DD + d]) = v0;
                const int r1 = r0 + 8;
                const int b1i = r1 >> 11, n1i = r1 & (NN - 1);
                *(float2*)(&Y[((((size_t)b1i * HH + h) * NN) + n1i) * DD + d]) = v1;
            } else {
                *(float2*)(&Y[(size_t)r0 * EE + c]) = v0;
                *(float2*)(&Y[(size_t)(r0 + 8) * EE + c]) = v1;
            }
        }
    }
}

// ---------------------------------------------------------------------------
// Flash attention. BQ=64, BKV=64, 8 warps (2x4).
// mma1 (3xbf16 m16n8k16): S^T[kv][q] = K . Q^T   K,Q bf16 hi/lo packed [row][d2]
// softmax column-wise over kv (online m/l), quirk: /sqrt(E)=32 post-softmax
// mma2 (1xtf32 m16n8k8): O[q][d] += P . V        P,V tf32-rounded (error ~1e-4)
// ---------------------------------------------------------------------------
__global__ __launch_bounds__(256)
void flash_mix(const float* __restrict__ qb,
               const float* __restrict__ kb,
               const float* __restrict__ vb,
               float* __restrict__ out)
{
    extern __shared__ char smraw[];
    uint32_t* Qh = (uint32_t*)smraw;       // [64 q][32 d2], swizzle (q&7)<<2
    uint32_t* Ql = Qh + 64 * 32;
    uint32_t* Kh = Ql + 64 * 32;           // [64 kv][32 d2]
    uint32_t* Kl = Kh + 64 * 32;
    uint32_t* Vs = Kl + 64 * 32;           // [kv][d ^ BXOR(kv)]  tf32
    float*    St = (float*)(Vs + 64 * 64); // [kv][q ^ ((kv&3)<<3)]
    float* mrow = St + 64 * 64;
    float* lrow = mrow + 64;
    float* arow = lrow + 64;
    float* pmax = arow + 64;               // [4][64]
    float* psum = pmax + 256;              // [4][64]

    const int tid  = threadIdx.x;
    const int lane = tid & 31;
    const int warp = tid >> 5;
    const int wm = warp >> 2, wn = warp & 3;
    const int g = lane >> 2, t4 = lane & 3;

    const int q0 = blockIdx.x * 64;
    const int bh = blockIdx.y;
    const int b  = bh >> 4;
    const int h  = bh & (HH - 1);

    if (tid < 64) { mrow[tid] = -1e30f; lrow[tid] = 0.f; }

    // Q load + bf16 hi/lo split (once per block, reused 32 tiles)
    const float* Qg = qb + ((size_t)bh * NN + q0) * DD;
    const int d4 = tid & 15, row0 = tid >> 4;
    #pragma unroll
    for (int i = 0; i < 4; ++i) {
        const int q = row0 + 16 * i;
        float4 v = *(const float4*)(Qg + (size_t)q * DD + d4 * 4);
        float h0, l0, h1, l1, h2, l2, h3, l3;
        bfsplit(v.x, h0, l0); bfsplit(v.y, h1, l1);
        bfsplit(v.z, h2, l2); bfsplit(v.w, h3, l3);
        const int idx = q * 32 + ((d4 * 2) ^ ((q & 7) << 2));
        *(uint2*)(&Qh[idx]) = make_uint2(packbf(h0, h1), packbf(h2, h3));
        *(uint2*)(&Ql[idx]) = make_uint2(packbf(l0, l1), packbf(l2, l3));
    }

    float oacc[2][2][4];
    #pragma unroll
    for (int i = 0; i < 2; ++i)
        #pragma unroll
        for (int j = 0; j < 2; ++j)
            #pragma unroll
            for (int c = 0; c < 4; ++c) oacc[i][j][c] = 0.f;

    const float* Kg = kb + (size_t)bh * NN * DD;
    const float* Vg = vb + (size_t)bh * NN * DD;

    for (int kv0 = 0; kv0 < NN; kv0 += 64) {
        __syncthreads();
        #pragma unroll
        for (int i = 0; i < 4; ++i) {
            const int kv = row0 + 16 * i;
            float4 kv4 = *(const float4*)(Kg + (size_t)(kv0 + kv) * DD + d4 * 4);
            float4 vv4 = *(const float4*)(Vg + (size_t)(kv0 + kv) * DD + d4 * 4);
            float h0, l0, h1, l1, h2, l2, h3, l3;
            bfsplit(kv4.x, h0, l0); bfsplit(kv4.y, h1, l1);
            bfsplit(kv4.z, h2, l2); bfsplit(kv4.w, h3, l3);
            const int kidx = kv * 32 + ((d4 * 2) ^ ((kv & 7) << 2));
            *(uint2*)(&Kh[kidx]) = make_uint2(packbf(h0, h1), packbf(h2, h3));
            *(uint2*)(&Kl[kidx]) = make_uint2(packbf(l0, l1), packbf(l2, l3));
            uint4 vu = make_uint4(f2tf(vv4.x), f2tf(vv4.y), f2tf(vv4.z), f2tf(vv4.w));
            *(uint4*)(&Vs[kv * 64 + ((d4 * 4) ^ BXOR(kv))]) = vu;
        }
        __syncthreads();

        // mma1: S^T = K . Q^T  (3xbf16, 4 chunks of k=16)
        float sacc[2][2][4];
        #pragma unroll
        for (int i = 0; i < 2; ++i)
            #pragma unroll
            for (int j = 0; j < 2; ++j)
                #pragma unroll
                for (int c = 0; c < 4; ++c) sacc[i][j][c] = 0.f;

        #pragma unroll
        for (int kk = 0; kk < 4; ++kk) {
            const int c = kk * 8 + t4;
            const int c2 = c + 4;
            uint32_t ah[2][4], al[2][4];
            #pragma unroll
            for (int mt = 0; mt < 2; ++mt) {
                const int r0 = wm * 32 + mt * 16 + g;
                const int sw = (r0 & 7) << 2;
                const int i0 = r0 * 32 + (c ^ sw);
                const int i1 = (r0 + 8) * 32 + (c ^ sw);
                const int i2 = r0 * 32 + (c2 ^ sw);
                const int i3 = (r0 + 8) * 32 + (c2 ^ sw);
                ah[mt][0] = Kh[i0]; al[mt][0] = Kl[i0];
                ah[mt][1] = Kh[i1]; al[mt][1] = Kl[i1];
                ah[mt][2] = Kh[i2]; al[mt][2] = Kl[i2];
                ah[mt][3] = Kh[i3]; al[mt][3] = Kl[i3];
            }
            uint32_t bh_[2][2], bl_[2][2];
            #pragma unroll
            for (int nt = 0; nt < 2; ++nt) {
                const int qb_ = wn * 16 + nt * 8 + g;
                const int sw = (qb_ & 7) << 2;
                const int i0 = qb_ * 32 + (c ^ sw);
                const int i1 = qb_ * 32 + (c2 ^ sw);
                bh_[nt][0] = Qh[i0]; bl_[nt][0] = Ql[i0];
                bh_[nt][1] = Qh[i1]; bl_[nt][1] = Ql[i1];
            }
            #pragma unroll
            for (int mt = 0; mt < 2; ++mt)
                #pragma unroll
                for (int nt = 0; nt < 2; ++nt)
                    mmabf_3x(sacc[mt][nt], ah[mt], al[mt], bh_[nt], bl_[nt]);
        }
        #pragma unroll
        for (int mt = 0; mt < 2; ++mt) {
            const int kvr = wm * 32 + mt * 16 + g;
            #pragma unroll
            for (int nt = 0; nt < 2; ++nt) {
                const int qc = wn * 16 + nt * 8 + 2 * t4;
                *(float2*)(&St[kvr * 64 + (qc ^ ((kvr & 3) << 3))]) =
                    make_float2(sacc[mt][nt][0], sacc[mt][nt][1]);
                *(float2*)(&St[(kvr + 8) * 64 + (qc ^ (((kvr + 8) & 3) << 3))]) =
                    make_float2(sacc[mt][nt][2], sacc[mt][nt][3]);
            }
        }
        __syncthreads();

        // online softmax over kv (columns of S^T); write back tf32-rounded p
        {
            const int q = tid & 63, kvg = tid >> 6;
            float sv[16];
            float mloc = -1e30f;
            #pragma unroll
            for (int r = 0; r < 16; ++r) {
                const int kv = kvg * 16 + r;
                sv[r] = St[kv * 64 + (q ^ ((kv & 3) << 3))];
                mloc = fmaxf(mloc, sv[r]);
            }
            pmax[kvg * 64 + q] = mloc;
            __syncthreads();
            const float mold = mrow[q];
            const float mnew = fmaxf(mold,
                fmaxf(fmaxf(pmax[q], pmax[64 + q]), fmaxf(pmax[128 + q], pmax[192 + q])));
            float sloc = 0.f;
            #pragma unroll
            for (int r = 0; r < 16; ++r) {
                const int kv = kvg * 16 + r;
                const float p = __expf(sv[r] - mnew);
                sloc += p;
                St[kv * 64 + (q ^ ((kv & 3) << 3))] = __uint_as_float(f2tf(p));
            }
            psum[kvg * 64 + q] = sloc;
            __syncthreads();
            if (kvg == 0) {
                const float alpha = __expf(mold - mnew);
                lrow[q] = lrow[q] * alpha + psum[q] + psum[64 + q] + psum[128 + q] + psum[192 + q];
                mrow[q] = mnew;
                arow[q] = alpha;
            }
            __syncthreads();
        }

        // rescale O accumulators
        #pragma unroll
        for (int mt = 0; mt < 2; ++mt) {
            const int qr = wm * 32 + mt * 16 + g;
            const float al0 = arow[qr], al1 = arow[qr + 8];
            #pragma unroll
            for (int nt = 0; nt < 2; ++nt) {
                oacc[mt][nt][0] *= al0; oacc[mt][nt][1] *= al0;
                oacc[mt][nt][2] *= al1; oacc[mt][nt][3] *= al1;
            }
        }

        // mma2: O += P . V  (single tf32 mma; P, V tf32-rounded)
        #pragma unroll
        for (int kk = 0; kk < 8; ++kk) {
            const int kvc = kk * 8 + t4;
            const int x0 = (kvc & 3) << 3;   // same for kvc and kvc+4
            uint32_t af[2][4];
            #pragma unroll
            for (int mt = 0; mt < 2; ++mt) {
                const int qr = wm * 32 + mt * 16 + g;
                af[mt][0] = __float_as_uint(St[kvc * 64 + (qr ^ x0)]);
                af[mt][1] = __float_as_uint(St[kvc * 64 + ((qr + 8) ^ x0)]);
                af[mt][2] = __float_as_uint(St[(kvc + 4) * 64 + (qr ^ x0)]);
                af[mt][3] = __float_as_uint(St[(kvc + 4) * 64 + ((qr + 8) ^ x0)]);
            }
            uint32_t bf[2][2];
            #pragma unroll
            for (int nt = 0; nt < 2; ++nt) {
                const int db = wn * 16 + nt * 8 + g;
                bf[nt][0] = Vs[kvc * 64 + (db ^ BXOR(kvc))];
                bf[nt][1] = Vs[(kvc + 4) * 64 + (db ^ BXOR(kvc + 4))];
            }
            #pragma unroll
            for (int mt = 0; mt < 2; ++mt)
                #pragma unroll
                for (int nt = 0; nt < 2; ++nt)
                    mma8(oacc[mt][nt][0], oacc[mt][nt][1], oacc[mt][nt][2], oacc[mt][nt][3],
                         af[mt][0], af[mt][1], af[mt][2], af[mt][3],
                         bf[nt][0], bf[nt][1]);
        }
    }

    // epilogue: /l, /sqrt(E)=32, merge heads
    #pragma unroll
    for (int mt = 0; mt < 2; ++mt) {
        const int qr = wm * 32 + mt * 16 + g;
        const float inv0 = 1.f / (lrow[qr] * 32.f);
        const float inv1 = 1.f / (lrow[qr + 8] * 32.f);
        #pragma unroll
        for (int nt = 0; nt < 2; ++nt) {
            const int dc = wn * 16 + nt * 8 + 2 * t4;
            *(float2*)(&out[((size_t)b * NN + q0 + qr) * EE + h * DD + dc]) =
                make_float2(oacc[mt][nt][0] * inv0, oacc[mt][nt][1] * inv0);
            *(float2*)(&out[((size_t)b * NN + q0 + qr + 8) * EE + h * DD + dc]) =
                make_float2(oacc[mt][nt][2] * inv1, oacc[mt][nt][3] * inv1);
        }
    }
}

// ---------------------------------------------------------------------------
// Launcher
// ---------------------------------------------------------------------------
extern "C" void kernel_launch(void* const* d_in, const int* in_sizes, int n_in,
                              void* d_out, int out_size)
{
    const float* queries = (const float*)d_in[0];
    const float* keys    = (const float*)d_in[1];
    const float* values  = (const float*)d_in[2];
    const float* Wq = (const float*)d_in[3];
    const float* bq = (const float*)d_in[4];
    const float* Wk = (const float*)d_in[5];
    const float* bk = (const float*)d_in[6];
    const float* Wv = (const float*)d_in[7];
    const float* bv = (const float*)d_in[8];
    const float* Wp = (const float*)d_in[9];
    const float* bp = (const float*)d_in[10];
    float* out = (float*)d_out;

    float *pq, *pk, *pv, *pao;
    cudaGetSymbolAddress((void**)&pq,  g_q);
    cudaGetSymbolAddress((void**)&pk,  g_k);
    cudaGetSymbolAddress((void**)&pv,  g_v);
    cudaGetSymbolAddress((void**)&pao, g_ao);

    const int gemm_smem = 4 * 128 * 16 * (int)sizeof(uint32_t); // 32768
    cudaFuncSetAttribute(gemm_bf16<1>,
                         cudaFuncAttributeMaxDynamicSharedMemorySize, gemm_smem);
    cudaFuncSetAttribute(gemm_bf16<0>,
                         cudaFuncAttributeMaxDynamicSharedMemorySize, gemm_smem);

    const dim3 gemm_grid(EE / 128, MTOT / 128);   // (8, 32)
    gemm_bf16<1><<<gemm_grid, 256, gemm_smem>>>(queries, Wq, bq, pq);
    gemm_bf16<1><<<gemm_grid, 256, gemm_smem>>>(keys,    Wk, bk, pk);
    gemm_bf16<1><<<gemm_grid, 256, gemm_smem>>>(values,  Wv, bv, pv);

    // Qh/Ql/Kh/Kl: 4*64*32 u32; Vs: 64*64 u32; St: 64*64 f32; rows: 3*64+2*256 f32
    const int fa_smem = (4 * 64 * 32 + 64 * 64 + 64 * 64) * 4 + (3 * 64 + 2 * 256) * 4; // 68096
    cudaFuncSetAttribute(flash_mix,
                         cudaFuncAttributeMaxDynamicSharedMemorySize, fa_smem);
    const dim3 fa_grid(NN / 64, BB * HH);         // (32, 32)
    flash_mix<<<fa_grid, 256, fa_smem>>>(pq, pk, pv, pao);

    gemm_bf16<0><<<gemm_grid, 256, gemm_smem>>>(pao, Wp, bp, out);
}

// round 8
// speedup vs baseline: 1.6287x; 1.1081x over previous
#include <cuda_runtime.h>
#include <cuda_bf16.h>
#include <stdint.h>

#define BB 2
#define NN 2048
#define EE 1024
#define HH 16
#define DD 64
#define MTOT (BB * NN)

// swizzle for tf32 V tile (row width 64 floats)
#define BXOR(k) (((((k) & 3) << 3)) | ((((k) & 4) << 2)))

// ---------------------------------------------------------------------------
// Scratch
// ---------------------------------------------------------------------------
__device__ float g_q [BB * HH * NN * DD];
__device__ float g_k [BB * HH * NN * DD];
__device__ float g_v [BB * HH * NN * DD];
__device__ float g_ao[(size_t)MTOT * EE];

// ---------------------------------------------------------------------------
// Helpers
// ---------------------------------------------------------------------------
__device__ __forceinline__ uint32_t f2tf(float x) {
    uint32_t u;
    asm("cvt.rna.tf32.f32 %0, %1;" : "=r"(u) : "f"(x));
    return u;
}

__device__ __forceinline__ void bfsplit(float x, float& h, float& l) {
    h = __bfloat162float(__float2bfloat16(x));
    l = x - h;
}

__device__ __forceinline__ uint32_t packbf(float a, float b) {
    __nv_bfloat162 t = __floats2bfloat162_rn(a, b);
    return *reinterpret_cast<uint32_t*>(&t);
}

// ldmatrix x4 (b16, non-transposed)
__device__ __forceinline__ void ldsm4(uint32_t& r0, uint32_t& r1, uint32_t& r2, uint32_t& r3,
                                      uint32_t addr) {
    asm volatile("ldmatrix.sync.aligned.m8n8.x4.shared.b16 {%0,%1,%2,%3}, [%4];"
        : "=r"(r0), "=r"(r1), "=r"(r2), "=r"(r3) : "r"(addr));
}

// tf32 m16n8k8 (used only for PV)
__device__ __forceinline__ void mma8(float& c0, float& c1, float& c2, float& c3,
                                     uint32_t a0, uint32_t a1, uint32_t a2, uint32_t a3,
                                     uint32_t b0, uint32_t b1) {
    asm volatile(
        "mma.sync.aligned.m16n8k8.row.col.f32.tf32.tf32.f32 "
        "{%0,%1,%2,%3}, {%4,%5,%6,%7}, {%8,%9}, {%0,%1,%2,%3};\n"
        : "+f"(c0), "+f"(c1), "+f"(c2), "+f"(c3)
        : "r"(a0), "r"(a1), "r"(a2), "r"(a3), "r"(b0), "r"(b1));
}

// bf16 m16n8k16
__device__ __forceinline__ void mmabf(float& c0, float& c1, float& c2, float& c3,
                                      uint32_t a0, uint32_t a1, uint32_t a2, uint32_t a3,
                                      uint32_t b0, uint32_t b1) {
    asm volatile(
        "mma.sync.aligned.m16n8k16.row.col.f32.bf16.bf16.f32 "
        "{%0,%1,%2,%3}, {%4,%5,%6,%7}, {%8,%9}, {%0,%1,%2,%3};\n"
        : "+f"(c0), "+f"(c1), "+f"(c2), "+f"(c3)
        : "r"(a0), "r"(a1), "r"(a2), "r"(a3), "r"(b0), "r"(b1));
}

__device__ __forceinline__ void mmabf_3x(float* c,
                                         const uint32_t* ah, const uint32_t* al,
                                         const uint32_t* bh, const uint32_t* bl) {
    mmabf(c[0], c[1], c[2], c[3], al[0], al[1], al[2], al[3], bh[0], bh[1]);
    mmabf(c[0], c[1], c[2], c[3], ah[0], ah[1], ah[2], ah[3], bl[0], bl[1]);
    mmabf(c[0], c[1], c[2], c[3], ah[0], ah[1], ah[2], ah[3], bh[0], bh[1]);
}

// ---------------------------------------------------------------------------
// 3xbf16 GEMM: Y[m,e] = X[m,:] . W[e,:] + bias[e]
// BM=128 BN=128 BK=32, 8 warps (2x4), warp tile 64x32, mma m16n8k16.
// smem row = [hi: 16 u32 | lo: 16 u32], 128B, swizzle ((row&7)<<2) on u32 col.
// Fragments loaded with ldmatrix.x4 (conflict-free under this swizzle).
// ---------------------------------------------------------------------------
template<int SCATTER>
__global__ __launch_bounds__(256, 2)
void gemm_bf16(const float* __restrict__ X,
               const float* __restrict__ W,
               const float* __restrict__ bias,
               float* __restrict__ Y)
{
    extern __shared__ uint32_t gsm[];
    uint32_t* Asm = gsm;                // [128][32]: hi cols 0-15, lo cols 16-31
    uint32_t* Bsm = Asm + 128 * 32;     // [128][32]

    const int tid  = threadIdx.x;
    const int lane = tid & 31;
    const int warp = tid >> 5;
    const int wm = warp >> 2, wn = warp & 3;
    const int g = lane >> 2, t4 = lane & 3;
    const int m0 = blockIdx.y * 128, n0 = blockIdx.x * 128;

    const int aRow = tid >> 3, aK4 = tid & 7;   // A loader
    const int bN = tid >> 1, bKh = tid & 1;     // B loader

    // ldmatrix per-lane geometry
    const int sel = lane >> 3;                   // 0..3
    const int lrow = lane & 7;
    const int swl = lrow << 2;                   // row swizzle (row&7)<<2, row≡lrow mod 8
    const int aoff = (sel & 1) * 8 + lrow;       // A: row within 16-tile
    const int akoff = (sel >> 1) * 4;            // A: k-half offset (u32)
    const int bnt = sel >> 1;                    // B: tile within pair
    const int bkoff = (sel & 1) * 4;             // B: k-half offset

    const uint32_t a_base = (uint32_t)__cvta_generic_to_shared(Asm);
    const uint32_t b_base = (uint32_t)__cvta_generic_to_shared(Bsm);

    float acc[4][4][4];
    #pragma unroll
    for (int i = 0; i < 4; ++i)
        #pragma unroll
        for (int j = 0; j < 4; ++j)
            #pragma unroll
            for (int c = 0; c < 4; ++c) acc[i][j][c] = 0.f;

    const float* Xb = X + (size_t)m0 * EE;
    const float* Wb = W + (size_t)n0 * EE;

    for (int kt = 0; kt < EE; kt += 32) {
        __syncthreads();
        #pragma unroll
        for (int i = 0; i < 4; ++i) {
            const int m = aRow + 32 * i;
            float4 v = *(const float4*)(Xb + (size_t)m * EE + kt + aK4 * 4);
            float h0, l0, h1, l1, h2, l2, h3, l3;
            bfsplit(v.x, h0, l0); bfsplit(v.y, h1, l1);
            bfsplit(v.z, h2, l2); bfsplit(v.w, h3, l3);
            const int sw = (m & 7) << 2;
            *(uint2*)(&Asm[m * 32 + ((aK4 * 2) ^ sw)]) =
                make_uint2(packbf(h0, h1), packbf(h2, h3));
            *(uint2*)(&Asm[m * 32 + ((16 + aK4 * 2) ^ sw)]) =
                make_uint2(packbf(l0, l1), packbf(l2, l3));
        }
        #pragma unroll
        for (int j = 0; j < 4; ++j) {
            const int kq = 2 * j + bKh;          // 0..7
            float4 v = *(const float4*)(Wb + (size_t)bN * EE + kt + kq * 4);
            float h0, l0, h1, l1, h2, l2, h3, l3;
            bfsplit(v.x, h0, l0); bfsplit(v.y, h1, l1);
            bfsplit(v.z, h2, l2); bfsplit(v.w, h3, l3);
            const int sw = (bN & 7) << 2;
            *(uint2*)(&Bsm[bN * 32 + ((kq * 2) ^ sw)]) =
                make_uint2(packbf(h0, h1), packbf(h2, h3));
            *(uint2*)(&Bsm[bN * 32 + ((16 + kq * 2) ^ sw)]) =
                make_uint2(packbf(l0, l1), packbf(l2, l3));
        }
        __syncthreads();

        #pragma unroll
        for (int kk = 0; kk < 2; ++kk) {
            const int c8 = kk * 8;
            uint32_t bh[4][2], bl[4][2];
            #pragma unroll
            for (int p = 0; p < 2; ++p) {
                const int brow = wn * 32 + (p * 2 + bnt) * 8 + lrow;
                const uint32_t ab = b_base + (brow * 32) * 4;
                ldsm4(bh[p*2][0], bh[p*2][1], bh[p*2+1][0], bh[p*2+1][1],
                      ab + (((c8 + bkoff) ^ swl) << 2));
                ldsm4(bl[p*2][0], bl[p*2][1], bl[p*2+1][0], bl[p*2+1][1],
                      ab + (((16 + c8 + bkoff) ^ swl) << 2));
            }
            #pragma unroll
            for (int mt = 0; mt < 4; ++mt) {
                const int arow = wm * 64 + mt * 16 + aoff;
                const uint32_t aa = a_base + (arow * 32) * 4;
                uint32_t ah[4], al[4];
                ldsm4(ah[0], ah[1], ah[2], ah[3], aa + (((c8 + akoff) ^ swl) << 2));
                ldsm4(al[0], al[1], al[2], al[3], aa + (((16 + c8 + akoff) ^ swl) << 2));
                #pragma unroll
                for (int nt = 0; nt < 4; ++nt)
                    mmabf_3x(acc[mt][nt], ah, al, bh[nt], bl[nt]);
            }
        }
    }

    #pragma unroll
    for (int mt = 0; mt < 4; ++mt) {
        const int r0 = m0 + wm * 64 + mt * 16 + g;
        #pragma unroll
        for (int nt = 0; nt < 4; ++nt) {
            const int c = n0 + wn * 32 + nt * 8 + 2 * t4;
            const float bv0 = bias[c], bv1 = bias[c + 1];
            float2 v0 = make_float2(acc[mt][nt][0] + bv0, acc[mt][nt][1] + bv1);
            float2 v1 = make_float2(acc[mt][nt][2] + bv0, acc[mt][nt][3] + bv1);
            if (SCATTER) {
                const int h = c >> 6, d = c & 63;
                const int b0i = r0 >> 11, n0i = r0 & (NN - 1);
                *(float2*)(&Y[((((size_t)b0i * HH + h) * NN) + n0i) * DD + d]) = v0;
                const int r1 = r0 + 8;
                const int b1i = r1 >> 11, n1i = r1 & (NN - 1);
                *(float2*)(&Y[((((size_t)b1i * HH + h) * NN) + n1i) * DD + d]) = v1;
            } else {
                *(float2*)(&Y[(size_t)r0 * EE + c]) = v0;
                *(float2*)(&Y[(size_t)(r0 + 8) * EE + c]) = v1;
            }
        }
    }
}

// ---------------------------------------------------------------------------
// Flash attention. BQ=64, BKV=64, 8 warps (2x4).
// mma1 (3xbf16 m16n8k16, ldmatrix): S^T[kv][q] = K . Q^T
// softmax column-wise over kv (online m/l), quirk: /sqrt(E)=32 post-softmax
// mma2 (1xtf32 m16n8k8): O[q][d] += P . V   P,V tf32-rounded (error ~1e-4)
// ---------------------------------------------------------------------------
__global__ __launch_bounds__(256)
void flash_mix(const float* __restrict__ qb,
               const float* __restrict__ kb,
               const float* __restrict__ vb,
               float* __restrict__ out)
{
    extern __shared__ char smraw[];
    uint32_t* Qh = (uint32_t*)smraw;       // [64 q][32 d2], swizzle (q&7)<<2
    uint32_t* Ql = Qh + 64 * 32;
    uint32_t* Kh = Ql + 64 * 32;           // [64 kv][32 d2]
    uint32_t* Kl = Kh + 64 * 32;
    uint32_t* Vs = Kl + 64 * 32;           // [kv][d ^ BXOR(kv)]  tf32
    float*    St = (float*)(Vs + 64 * 64); // [kv][q ^ ((kv&3)<<3)]
    float* mrow = St + 64 * 64;
    float* lrow = mrow + 64;
    float* arow = lrow + 64;
    float* pmax = arow + 64;               // [4][64]
    float* psum = pmax + 256;              // [4][64]

    const int tid  = threadIdx.x;
    const int lane = tid & 31;
    const int warp = tid >> 5;
    const int wm = warp >> 2, wn = warp & 3;
    const int g = lane >> 2, t4 = lane & 3;

    const int q0 = blockIdx.x * 64;
    const int bh = blockIdx.y;
    const int b  = bh >> 4;
    const int h  = bh & (HH - 1);

    // ldmatrix per-lane geometry
    const int sel = lane >> 3;
    const int lrowm = lane & 7;
    const int swl = lrowm << 2;
    const int aoff = (sel & 1) * 8 + lrowm;      // A (K) tiles
    const int akoff = (sel >> 1) * 4;
    const int bnt = sel >> 1;                    // B (Q) tiles
    const int bkoff = (sel & 1) * 4;

    const uint32_t qh_base = (uint32_t)__cvta_generic_to_shared(Qh);
    const uint32_t ql_base = (uint32_t)__cvta_generic_to_shared(Ql);
    const uint32_t kh_base = (uint32_t)__cvta_generic_to_shared(Kh);
    const uint32_t kl_base = (uint32_t)__cvta_generic_to_shared(Kl);

    if (tid < 64) { mrow[tid] = -1e30f; lrow[tid] = 0.f; }

    // Q load + bf16 hi/lo split (once per block, reused 32 tiles)
    const float* Qg = qb + ((size_t)bh * NN + q0) * DD;
    const int d4 = tid & 15, row0 = tid >> 4;
    #pragma unroll
    for (int i = 0; i < 4; ++i) {
        const int q = row0 + 16 * i;
        float4 v = *(const float4*)(Qg + (size_t)q * DD + d4 * 4);
        float h0, l0, h1, l1, h2, l2, h3, l3;
        bfsplit(v.x, h0, l0); bfsplit(v.y, h1, l1);
        bfsplit(v.z, h2, l2); bfsplit(v.w, h3, l3);
        const int idx = q * 32 + ((d4 * 2) ^ ((q & 7) << 2));
        *(uint2*)(&Qh[idx]) = make_uint2(packbf(h0, h1), packbf(h2, h3));
        *(uint2*)(&Ql[idx]) = make_uint2(packbf(l0, l1), packbf(l2, l3));
    }

    float oacc[2][2][4];
    #pragma unroll
    for (int i = 0; i < 2; ++i)
        #pragma unroll
        for (int j = 0; j < 2; ++j)
            #pragma unroll
            for (int c = 0; c < 4; ++c) oacc[i][j][c] = 0.f;

    const float* Kg = kb + (size_t)bh * NN * DD;
    const float* Vg = vb + (size_t)bh * NN * DD;

    for (int kv0 = 0; kv0 < NN; kv0 += 64) {
        __syncthreads();
        #pragma unroll
        for (int i = 0; i < 4; ++i) {
            const int kv = row0 + 16 * i;
            float4 kv4 = *(const float4*)(Kg + (size_t)(kv0 + kv) * DD + d4 * 4);
            float4 vv4 = *(const float4*)(Vg + (size_t)(kv0 + kv) * DD + d4 * 4);
            float h0, l0, h1, l1, h2, l2, h3, l3;
            bfsplit(kv4.x, h0, l0); bfsplit(kv4.y, h1, l1);
            bfsplit(kv4.z, h2, l2); bfsplit(kv4.w, h3, l3);
            const int kidx = kv * 32 + ((d4 * 2) ^ ((kv & 7) << 2));
            *(uint2*)(&Kh[kidx]) = make_uint2(packbf(h0, h1), packbf(h2, h3));
            *(uint2*)(&Kl[kidx]) = make_uint2(packbf(l0, l1), packbf(l2, l3));
            uint4 vu = make_uint4(f2tf(vv4.x), f2tf(vv4.y), f2tf(vv4.z), f2tf(vv4.w));
            *(uint4*)(&Vs[kv * 64 + ((d4 * 4) ^ BXOR(kv))]) = vu;
        }
        __syncthreads();

        // mma1: S^T = K . Q^T  (3xbf16, 4 chunks of k=16, ldmatrix fragments)
        float sacc[2][2][4];
        #pragma unroll
        for (int i = 0; i < 2; ++i)
            #pragma unroll
            for (int j = 0; j < 2; ++j)
                #pragma unroll
                for (int c = 0; c < 4; ++c) sacc[i][j][c] = 0.f;

        #pragma unroll
        for (int kk = 0; kk < 4; ++kk) {
            const int c8 = kk * 8;
            uint32_t bh_[2][2], bl_[2][2];
            {
                const int brow = wn * 16 + bnt * 8 + lrowm;
                const uint32_t off = ((c8 + bkoff) ^ swl) << 2;
                ldsm4(bh_[0][0], bh_[0][1], bh_[1][0], bh_[1][1],
                      qh_base + (brow * 32) * 4 + off);
                ldsm4(bl_[0][0], bl_[0][1], bl_[1][0], bl_[1][1],
                      ql_base + (brow * 32) * 4 + off);
            }
            #pragma unroll
            for (int mt = 0; mt < 2; ++mt) {
                const int arow = wm * 32 + mt * 16 + aoff;
                const uint32_t off = ((c8 + akoff) ^ swl) << 2;
                uint32_t ah[4], al[4];
                ldsm4(ah[0], ah[1], ah[2], ah[3], kh_base + (arow * 32) * 4 + off);
                ldsm4(al[0], al[1], al[2], al[3], kl_base + (arow * 32) * 4 + off);
                #pragma unroll
                for (int nt = 0; nt < 2; ++nt)
                    mmabf_3x(sacc[mt][nt], ah, al, bh_[nt], bl_[nt]);
            }
        }
        #pragma unroll
        for (int mt = 0; mt < 2; ++mt) {
            const int kvr = wm * 32 + mt * 16 + g;
            #pragma unroll
            for (int nt = 0; nt < 2; ++nt) {
                const int qc = wn * 16 + nt * 8 + 2 * t4;
                *(float2*)(&St[kvr * 64 + (qc ^ ((kvr & 3) << 3))]) =
                    make_float2(sacc[mt][nt][0], sacc[mt][nt][1]);
                *(float2*)(&St[(kvr + 8) * 64 + (qc ^ (((kvr + 8) & 3) << 3))]) =
                    make_float2(sacc[mt][nt][2], sacc[mt][nt][3]);
            }
        }
        __syncthreads();

        // online softmax over kv (columns of S^T); write back tf32-rounded p
        {
            const int q = tid & 63, kvg = tid >> 6;
            float sv[16];
            float mloc = -1e30f;
            #pragma unroll
            for (int r = 0; r < 16; ++r) {
                const int kv = kvg * 16 + r;
                sv[r] = St[kv * 64 + (q ^ ((kv & 3) << 3))];
                mloc = fmaxf(mloc, sv[r]);
            }
            pmax[kvg * 64 + q] = mloc;
            __syncthreads();
            const float mold = mrow[q];
            const float mnew = fmaxf(mold,
                fmaxf(fmaxf(pmax[q], pmax[64 + q]), fmaxf(pmax[128 + q], pmax[192 + q])));
            float sloc = 0.f;
            #pragma unroll
            for (int r = 0; r < 16; ++r) {
                const int kv = kvg * 16 + r;
                const float p = __expf(sv[r] - mnew);
                sloc += p;
                St[kv * 64 + (q ^ ((kv & 3) << 3))] = __uint_as_float(f2tf(p));
            }
            psum[kvg * 64 + q] = sloc;
            __syncthreads();
            if (kvg == 0) {
                const float alpha = __expf(mold - mnew);
                lrow[q] = lrow[q] * alpha + psum[q] + psum[64 + q] + psum[128 + q] + psum[192 + q];
                mrow[q] = mnew;
                arow[q] = alpha;
            }
            __syncthreads();
        }

        // rescale O accumulators
        #pragma unroll
        for (int mt = 0; mt < 2; ++mt) {
            const int qr = wm * 32 + mt * 16 + g;
            const float al0 = arow[qr], al1 = arow[qr + 8];
            #pragma unroll
            for (int nt = 0; nt < 2; ++nt) {
                oacc[mt][nt][0] *= al0; oacc[mt][nt][1] *= al0;
                oacc[mt][nt][2] *= al1; oacc[mt][nt][3] *= al1;
            }
        }

        // mma2: O += P . V  (single tf32 mma; P, V tf32-rounded)
        #pragma unroll
        for (int kk = 0; kk < 8; ++kk) {
            const int kvc = kk * 8 + t4;
            const int x0 = (kvc & 3) << 3;   // same for kvc and kvc+4
            uint32_t af[2][4];
            #pragma unroll
            for (int mt = 0; mt < 2; ++mt) {
                const int qr = wm * 32 + mt * 16 + g;
                af[mt][0] = __float_as_uint(St[kvc * 64 + (qr ^ x0)]);
                af[mt][1] = __float_as_uint(St[kvc * 64 + ((qr + 8) ^ x0)]);
                af[mt][2] = __float_as_uint(St[(kvc + 4) * 64 + (qr ^ x0)]);
                af[mt][3] = __float_as_uint(St[(kvc + 4) * 64 + ((qr + 8) ^ x0)]);
            }
            uint32_t bf[2][2];
            #pragma unroll
            for (int nt = 0; nt < 2; ++nt) {
                const int db = wn * 16 + nt * 8 + g;
                bf[nt][0] = Vs[kvc * 64 + (db ^ BXOR(kvc))];
                bf[nt][1] = Vs[(kvc + 4) * 64 + (db ^ BXOR(kvc + 4))];
            }
            #pragma unroll
            for (int mt = 0; mt < 2; ++mt)
                #pragma unroll
                for (int nt = 0; nt < 2; ++nt)
                    mma8(oacc[mt][nt][0], oacc[mt][nt][1], oacc[mt][nt][2], oacc[mt][nt][3],
                         af[mt][0], af[mt][1], af[mt][2], af[mt][3],
                         bf[nt][0], bf[nt][1]);
        }
    }

    // epilogue: /l, /sqrt(E)=32, merge heads
    #pragma unroll
    for (int mt = 0; mt < 2; ++mt) {
        const int qr = wm * 32 + mt * 16 + g;
        const float inv0 = 1.f / (lrow[qr] * 32.f);
        const float inv1 = 1.f / (lrow[qr + 8] * 32.f);
        #pragma unroll
        for (int nt = 0; nt < 2; ++nt) {
            const int dc = wn * 16 + nt * 8 + 2 * t4;
            *(float2*)(&out[((size_t)b * NN + q0 + qr) * EE + h * DD + dc]) =
                make_float2(oacc[mt][nt][0] * inv0, oacc[mt][nt][1] * inv0);
            *(float2*)(&out[((size_t)b * NN + q0 + qr + 8) * EE + h * DD + dc]) =
                make_float2(oacc[mt][nt][2] * inv1, oacc[mt][nt][3] * inv1);
        }
    }
}

// ---------------------------------------------------------------------------
// Launcher
// ---------------------------------------------------------------------------
extern "C" void kernel_launch(void* const* d_in, const int* in_sizes, int n_in,
                              void* d_out, int out_size)
{
    const float* queries = (const float*)d_in[0];
    const float* keys    = (const float*)d_in[1];
    const float* values  = (const float*)d_in[2];
    const float* Wq = (const float*)d_in[3];
    const float* bq = (const float*)d_in[4];
    const float* Wk = (const float*)d_in[5];
    const float* bk = (const float*)d_in[6];
    const float* Wv = (const float*)d_in[7];
    const float* bv = (const float*)d_in[8];
    const float* Wp = (const float*)d_in[9];
    const float* bp = (const float*)d_in[10];
    float* out = (float*)d_out;

    float *pq, *pk, *pv, *pao;
    cudaGetSymbolAddress((void**)&pq,  g_q);
    cudaGetSymbolAddress((void**)&pk,  g_k);
    cudaGetSymbolAddress((void**)&pv,  g_v);
    cudaGetSymbolAddress((void**)&pao, g_ao);

    const int gemm_smem = 2 * 128 * 32 * (int)sizeof(uint32_t); // 32768
    cudaFuncSetAttribute(gemm_bf16<1>,
                         cudaFuncAttributeMaxDynamicSharedMemorySize, gemm_smem);
    cudaFuncSetAttribute(gemm_bf16<0>,
                         cudaFuncAttributeMaxDynamicSharedMemorySize, gemm_smem);

    const dim3 gemm_grid(EE / 128, MTOT / 128);   // (8, 32)
    gemm_bf16<1><<<gemm_grid, 256, gemm_smem>>>(queries, Wq, bq, pq);
    gemm_bf16<1><<<gemm_grid, 256, gemm_smem>>>(keys,    Wk, bk, pk);
    gemm_bf16<1><<<gemm_grid, 256, gemm_smem>>>(values,  Wv, bv, pv);

    // Qh/Ql/Kh/Kl: 4*64*32 u32; Vs: 64*64 u32; St: 64*64 f32; rows: 3*64+2*256 f32
    const int fa_smem = (4 * 64 * 32 + 64 * 64 + 64 * 64) * 4 + (3 * 64 + 2 * 256) * 4; // 68096
    cudaFuncSetAttribute(flash_mix,
                         cudaFuncAttributeMaxDynamicSharedMemorySize, fa_smem);
    const dim3 fa_grid(NN / 64, BB * HH);         // (32, 32)
    flash_mix<<<fa_grid, 256, fa_smem>>>(pq, pk, pv, pao);

    gemm_bf16<0><<<gemm_grid, 256, gemm_smem>>>(pao, Wp, bp, out);
}